// round 15
// baseline (speedup 1.0000x reference)
#include <cuda_runtime.h>
#include <cuda_bf16.h>
#include <cstdint>

// ===========================================================================
// 4D CNN (6 conv4d 3^4 SAME + 5 scalar PReLU).
// Layers 1-5: warp-level mma.sync (HMMA) implicit GEMM, per-tap K=32 GEMMs,
// fp32 accum, split-bf16 (AhBh + AhBl + AlBh). B operands from precomputed
// register-fragment tables in global. Activation slices staged with
// cp.async (LDGSTS) into a DOUBLE-BUFFERED smem ring so staging of slice
// p+1 overlaps MMA compute on slice p (R14 ncu: tensor 79%, idle = staging
// serialization). Last layer computes only the n8 tile with its 2 channels.
// Layer 0 (ci=2): FFMA2 direct conv with split-output epilogue.
// ===========================================================================

static constexpr int Ld = 16;
static constexpr int SP = Ld * Ld * Ld * Ld;  // 65536

// ---- scratch (device globals: allowed) ----
__device__ __nv_bfloat16 g_actH0[8 * SP * 32];
__device__ __nv_bfloat16 g_actL0[8 * SP * 32];
__device__ __nv_bfloat16 g_actH1[8 * SP * 32];
__device__ __nv_bfloat16 g_actL1[8 * SP * 32];
__device__ uint2         g_wfrag[81 * 512];    // [tap][s][ks][nt][lane] b0,b1
__device__ float         g_wt[32 * 81 * 32];   // layer0 transposed weights

// ===========================================================================
// mma.sync / ldmatrix / cp.async helpers
// ===========================================================================
__device__ __forceinline__ uint32_t smem_to_u32(const void* p) {
    uint32_t a;
    asm("{ .reg .u64 t; cvta.to.shared.u64 t, %1; cvt.u32.u64 %0, t; }"
        : "=r"(a) : "l"(p));
    return a;
}
__device__ __forceinline__ void ldm_x4(uint32_t* r, uint32_t a) {
    asm volatile("ldmatrix.sync.aligned.m8n8.x4.shared.b16 {%0,%1,%2,%3}, [%4];"
        : "=r"(r[0]), "=r"(r[1]), "=r"(r[2]), "=r"(r[3]) : "r"(a));
}
__device__ __forceinline__ void mma_bf16(float* d, const uint32_t* a,
                                         uint32_t b0, uint32_t b1) {
    asm volatile("mma.sync.aligned.m16n8k16.row.col.f32.bf16.bf16.f32 "
        "{%0,%1,%2,%3}, {%4,%5,%6,%7}, {%8,%9}, {%0,%1,%2,%3};"
        : "+f"(d[0]), "+f"(d[1]), "+f"(d[2]), "+f"(d[3])
        : "r"(a[0]), "r"(a[1]), "r"(a[2]), "r"(a[3]), "r"(b0), "r"(b1));
}
__device__ __forceinline__ void cp16(uint32_t s, const void* g, bool ok) {
    int sz = ok ? 16 : 0;   // src_size 0 -> zero-fill 16B
    asm volatile("cp.async.cg.shared.global [%0], [%1], 16, %2;"
        :: "r"(s), "l"(g), "r"(sz));
}
#define CP_COMMIT() asm volatile("cp.async.commit_group;" ::: "memory")
#define CP_WAIT0()  asm volatile("cp.async.wait_group 0;" ::: "memory")

// ===========================================================================
// f32x2 helpers (layer 0)
// ===========================================================================
using u64 = unsigned long long;
__device__ __forceinline__ u64 dup2(float x) {
    u64 r; asm("mov.b64 %0, {%1, %1};" : "=l"(r) : "f"(x)); return r;
}
__device__ __forceinline__ u64 fma2(u64 a, u64 b, u64 c) {
    u64 d; asm("fma.rn.f32x2 %0, %1, %2, %3;" : "=l"(d) : "l"(a), "l"(b), "l"(c));
    return d;
}
__device__ __forceinline__ void unpack2(u64 v, float& lo, float& hi) {
    asm("mov.b64 {%0, %1}, %2;" : "=f"(lo), "=f"(hi) : "l"(v));
}
__device__ __forceinline__ uint32_t packbf(__nv_bfloat16 a, __nv_bfloat16 b) {
    __nv_bfloat162 t(a, b);           // a -> low 16 bits
    return *reinterpret_cast<uint32_t*>(&t);
}

// ===========================================================================
// Weight prep
// ===========================================================================
__global__ void transpose_w_kernel(const float* __restrict__ w,
                                   float* __restrict__ wt, int CO, int CI) {
    int idx = blockIdx.x * blockDim.x + threadIdx.x;
    int total = CO * CI * 81;
    if (idx >= total) return;
    int co  = idx / (CI * 81);
    int rem = idx - co * (CI * 81);
    int ci  = rem / 81;
    int tap = rem - ci * 81;
    wt[(ci * 81 + tap) * CO + co] = w[idx];
}

// W[CO][32][81] fp32 -> per-lane B fragments for mma.m16n8k16.row.col.
// [tap][split][ks][nt][lane] -> uint2; co>=CO zero-padded.
__global__ void prep_w_frag(const float* __restrict__ w, int CO,
                            uint2* __restrict__ gf) {
    int idx = blockIdx.x * blockDim.x + threadIdx.x;
    if (idx >= 81 * 512) return;
    int lane = idx & 31;
    int nt   = (idx >> 5) & 3;
    int ks   = (idx >> 7) & 1;
    int s    = (idx >> 8) & 1;
    int tap  = idx >> 9;
    int n  = nt * 8 + (lane >> 2);
    int k0 = (lane & 3) * 2 + ks * 16;
    auto valbf = [&](int ci) -> __nv_bfloat16 {
        float v = (n < CO) ? w[((size_t)n * 32 + ci) * 81 + tap] : 0.f;
        __nv_bfloat16 hi = __float2bfloat16(v);
        if (s == 0) return hi;
        return __float2bfloat16(v - __bfloat162float(hi));
    };
    uint2 r;
    r.x = packbf(valbf(k0),     valbf(k0 + 1));
    r.y = packbf(valbf(k0 + 8), valbf(k0 + 9));
    gf[idx] = r;
}

// ===========================================================================
// Layer 0: FFMA2 direct conv (ci=2), split bf16 channels-last output.
// ===========================================================================
template<int C_IN, int CI_CHUNK, int T1, int T2, int T3>
__global__ void __launch_bounds__(256)
conv4d_l0_kernel(const float* __restrict__ in,
                 const float* __restrict__ wt,
                 const float* __restrict__ slope_p,
                 __nv_bfloat16* __restrict__ outH,
                 __nv_bfloat16* __restrict__ outL)
{
    constexpr int C_OUT = 32, CO_PER = 8, CP2 = CO_PER / 2;
    constexpr int H1 = T1 + 2, H2 = T2 + 2, H3 = T3 + 2, H4 = 20;
    constexpr int VG = T1 * T2 * T3 * 2;
    constexpr int NT = VG * (C_OUT / CO_PER);
    constexpr int SMCH = H1 * H2 * H3 * H4;

    __shared__ float sx[CI_CHUNK * SMCH];

    constexpr int NB2 = 16 / T2, NB3 = 16 / T3;
    int tb = blockIdx.x;
    int b3 = tb % NB3; tb /= NB3;
    int b2 = tb % NB2; tb /= NB2;
    int b1 = tb;
    int n  = blockIdx.y;

    int tid = threadIdx.x;
    int cog = tid / VG;
    int vg  = tid - cog * VG;
    int v4h = vg & 1;
    int t   = vg >> 1;
    int v3  = t % T3; t /= T3;
    int v2  = t % T2; t /= T2;
    int v1  = t;
    int co0 = cog * CO_PER;

    u64 accP[CP2][8];
#pragma unroll
    for (int c2 = 0; c2 < CP2; ++c2)
#pragma unroll
        for (int j = 0; j < 8; ++j) accP[c2][j] = 0ull;

    const float* inb = in + (size_t)n * C_IN * SP;

    for (int cc = 0; cc < C_IN; cc += CI_CHUNK) {
        __syncthreads();
        constexpr int LOADN = CI_CHUNK * H1 * H2 * H3 * 18;
        for (int idx = tid; idx < LOADN; idx += NT) {
            int i4 = idx % 18; int r = idx / 18;
            int i3 = r % H3; r /= H3;
            int i2 = r % H2; r /= H2;
            int i1 = r % H1; r /= H1;
            int g1 = b1 * T1 - 1 + i1, g2 = b2 * T2 - 1 + i2;
            int g3 = b3 * T3 - 1 + i3, g4 = i4 - 1;
            float v = 0.f;
            if ((unsigned)g1 < 16u && (unsigned)g2 < 16u &&
                (unsigned)g3 < 16u && (unsigned)g4 < 16u)
                v = inb[(size_t)(cc + r) * SP +
                        (((g1 * 16 + g2) * 16 + g3) * 16 + g4)];
            sx[r * SMCH + ((i1 * H2 + i2) * H3 + i3) * H4 + i4] = v;
        }
        __syncthreads();

#pragma unroll 1
        for (int ci = 0; ci < CI_CHUNK; ++ci) {
            const float* wp = wt + ((size_t)(cc + ci) * 81) * C_OUT + co0;
            const float* sc = sx + ci * SMCH;
#pragma unroll 1
            for (int o1 = 0; o1 < 3; ++o1)
#pragma unroll 1
            for (int o2 = 0; o2 < 3; ++o2)
#pragma unroll 1
            for (int o3 = 0; o3 < 3; ++o3) {
                const float* srow =
                    sc + (((v1 + o1) * H2 + (v2 + o2)) * H3 + (v3 + o3)) * H4
                       + v4h * 8;
                u64 rxd[10];
#pragma unroll
                for (int j = 0; j < 10; ++j) rxd[j] = dup2(srow[j]);
                const float* wo = wp + (((o1 * 3 + o2) * 3 + o3) * 3) * C_OUT;
#pragma unroll
                for (int o4 = 0; o4 < 3; ++o4) {
                    const u64* wp64 = reinterpret_cast<const u64*>(wo + o4 * C_OUT);
                    u64 w2[CP2];
#pragma unroll
                    for (int c2 = 0; c2 < CP2; ++c2) w2[c2] = wp64[c2];
#pragma unroll
                    for (int j = 0; j < 8; ++j)
#pragma unroll
                        for (int c2 = 0; c2 < CP2; ++c2)
                            accP[c2][j] = fma2(w2[c2], rxd[j + o4], accP[c2][j]);
                }
            }
        }
    }

    float acc[CO_PER][8];
#pragma unroll
    for (int c2 = 0; c2 < CP2; ++c2)
#pragma unroll
        for (int j = 0; j < 8; ++j)
            unpack2(accP[c2][j], acc[2 * c2][j], acc[2 * c2 + 1][j]);

    float slope = *slope_p;
    int d1 = b1 * T1 + v1, d2 = b2 * T2 + v2, d3 = b3 * T3 + v3;
    size_t sidx = (((size_t)d1 * 16 + d2) * 16 + d3) * 16 + v4h * 8;

#pragma unroll
    for (int j = 0; j < 8; ++j) {
        uint32_t HW[4], LW[4];
#pragma unroll
        for (int w = 0; w < 4; ++w) {
            float v0 = acc[2 * w][j], v1 = acc[2 * w + 1][j];
            v0 = (v0 < 0.f) ? slope * v0 : v0;
            v1 = (v1 < 0.f) ? slope * v1 : v1;
            __nv_bfloat16 h0 = __float2bfloat16(v0);
            __nv_bfloat16 h1 = __float2bfloat16(v1);
            float l0 = v0 - __bfloat162float(h0);
            float l1 = v1 - __bfloat162float(h1);
            HW[w] = packbf(h0, h1);
            LW[w] = packbf(__float2bfloat16(l0), __float2bfloat16(l1));
        }
        size_t e = ((size_t)n * SP + sidx + j) * 32 + co0;
        *reinterpret_cast<uint4*>(outH + e) = *reinterpret_cast<uint4*>(HW);
        *reinterpret_cast<uint4*>(outL + e) = *reinterpret_cast<uint4*>(LW);
    }
}

// ===========================================================================
// HMMA conv layer (ci=32): per-tap m16n8k16 MMAs, fp32 register accum.
// CTA = one (n, d1, d2) plane -> 256 positions. Warp w owns d3 rows
// {2w, 2w+1}. Double-buffered cp.async slice staging: slice p+1 in flight
// while MMAs consume slice p. smem = 2 x (25920 hi + 25920 lo) = 103680 B
// -> 2 CTAs/SM.
// ===========================================================================
static constexpr int HW_LO   = 25920;           // lo offset within a buffer
static constexpr int HW_BUF  = 51840;           // buffer stride
static constexpr int HW_SMEM = 103680;

template<int NTT, bool LAST>
__global__ void __launch_bounds__(256, 2)
conv4d_mma_kernel(const __nv_bfloat16* __restrict__ aH,
                  const __nv_bfloat16* __restrict__ aL,
                  const uint2* __restrict__ wf,
                  const float* __restrict__ slope_p,
                  __nv_bfloat16* __restrict__ oH,
                  __nv_bfloat16* __restrict__ oL,
                  float* __restrict__ oF)
{
    extern __shared__ char sm[];
    const uint32_t sb = smem_to_u32(sm);

    int tid  = threadIdx.x;
    int wid  = tid >> 5;
    int lane = tid & 31;
    int lrow = lane & 15;
    uint32_t laneA = (uint32_t)lrow * 80 + ((lane >> 4) & 1) * 16;

    int n  = blockIdx.y;
    int d1 = blockIdx.x >> 4, d2 = blockIdx.x & 15;
    const size_t nbase = (size_t)n * SP;

    float d[2][NTT][4];
#pragma unroll
    for (int m = 0; m < 2; ++m)
#pragma unroll
        for (int nt = 0; nt < NTT; ++nt)
#pragma unroll
            for (int r = 0; r < 4; ++r) d[m][nt][r] = 0.f;

    // ---- async slice staging: [18 d3][18 d4][32 ci] hi & lo, 80B pitch ----
    auto stage = [&](int o12, uint32_t bufbase) {
        int o1 = o12 / 3, o2 = o12 - (o12 / 3) * 3;
        int g1 = d1 + o1 - 1, g2 = d2 + o2 - 1;
        bool rowok = ((unsigned)g1 < 16u) && ((unsigned)g2 < 16u);
        for (int i = tid; i < 1296; i += 256) {     // 324 pts x 4 16B-chunks
            int pt = i >> 2, ch = i & 3;
            int s3 = pt / 18, s4 = pt - s3 * 18;
            int g3 = s3 - 1, g4 = s4 - 1;
            bool ok = rowok && (unsigned)g3 < 16u && (unsigned)g4 < 16u;
            size_t p = 0;
            if (ok) p = nbase + (size_t)(((g1 * 16 + g2) * 16 + g3) * 16 + g4);
            uint32_t so = bufbase + (uint32_t)(pt * 80 + ch * 16);
            cp16(so,         (const char*)(aH + p * 32) + ch * 16, ok);
            cp16(so + HW_LO, (const char*)(aL + p * 32) + ch * 16, ok);
        }
        CP_COMMIT();
    };

    stage(0, sb);                       // prologue: slice 0 -> buffer 0

#pragma unroll 1
    for (int o12 = 0; o12 < 9; ++o12) {
        CP_WAIT0();                     // slice o12 landed (per-thread)
        __syncthreads();                // ... and visible to all warps
        if (o12 < 8) stage(o12 + 1, sb + (uint32_t)((o12 + 1) & 1) * HW_BUF);

        const uint32_t cb = sb + (uint32_t)(o12 & 1) * HW_BUF;

#pragma unroll 1
        for (int o3 = 0; o3 < 3; ++o3)
#pragma unroll 1
        for (int o4 = 0; o4 < 3; ++o4) {
            int tap = o12 * 9 + o3 * 3 + o4;
            const uint2* wfH = wf + (size_t)tap * 512 + lane;
            const uint2* wfL = wfH + 256;
            int pr0 = ((wid * 2 + 0 + o3) * 18 + o4) * 80;
            uint32_t aH0 = cb + pr0 + laneA;
            uint32_t aH1 = aH0 + 1440;               // +1 d3 row (18*80)
            uint32_t aL0 = aH0 + HW_LO;
            uint32_t aL1 = aL0 + 1440;

#pragma unroll
            for (int ks = 0; ks < 2; ++ks) {
                uint2 BH[NTT], BL[NTT];
#pragma unroll
                for (int nt = 0; nt < NTT; ++nt) {
                    BH[nt] = wfH[ks * 128 + nt * 32];
                    BL[nt] = wfL[ks * 128 + nt * 32];
                }
                uint32_t ah[2][4], al[2][4];
                ldm_x4(ah[0], aH0 + ks * 32);
                ldm_x4(ah[1], aH1 + ks * 32);
                ldm_x4(al[0], aL0 + ks * 32);
                ldm_x4(al[1], aL1 + ks * 32);
#pragma unroll
                for (int m = 0; m < 2; ++m)
#pragma unroll
                    for (int nt = 0; nt < NTT; ++nt) {
                        mma_bf16(d[m][nt], ah[m], BH[nt].x, BH[nt].y);
                        mma_bf16(d[m][nt], ah[m], BL[nt].x, BL[nt].y);
                        mma_bf16(d[m][nt], al[m], BH[nt].x, BH[nt].y);
                    }
            }
        }
    }

    // ---- epilogue ----
    int gID = lane >> 2, tig = lane & 3;
    if (!LAST) {
        float slope = *slope_p;
#pragma unroll
        for (int m = 0; m < 2; ++m) {
            int p3 = wid * 2 + m;
#pragma unroll
            for (int nt = 0; nt < NTT; ++nt) {
                int co = nt * 8 + tig * 2;
#pragma unroll
                for (int rr = 0; rr < 2; ++rr) {
                    int p4 = gID + rr * 8;
                    float v0 = d[m][nt][rr * 2 + 0];
                    float v1 = d[m][nt][rr * 2 + 1];
                    v0 = (v0 < 0.f) ? slope * v0 : v0;
                    v1 = (v1 < 0.f) ? slope * v1 : v1;
                    __nv_bfloat16 h0 = __float2bfloat16(v0);
                    __nv_bfloat16 h1 = __float2bfloat16(v1);
                    float l0 = v0 - __bfloat162float(h0);
                    float l1 = v1 - __bfloat162float(h1);
                    size_t pg = (size_t)(((d1 * 16 + d2) * 16 + p3) * 16 + p4);
                    size_t e = (nbase + pg) * 32 + co;
                    *reinterpret_cast<uint32_t*>(oH + e) = packbf(h0, h1);
                    *reinterpret_cast<uint32_t*>(oL + e) =
                        packbf(__float2bfloat16(l0), __float2bfloat16(l1));
                }
            }
        }
    } else {
        if (tig == 0) {
#pragma unroll
            for (int m = 0; m < 2; ++m) {
                int p3 = wid * 2 + m;
#pragma unroll
                for (int rr = 0; rr < 2; ++rr) {
                    int p4 = gID + rr * 8;
                    size_t pg = (size_t)(((d1 * 16 + d2) * 16 + p3) * 16 + p4);
                    oF[(size_t)n * 2 * SP + pg]      = d[m][0][rr * 2 + 0];
                    oF[(size_t)n * 2 * SP + SP + pg] = d[m][0][rr * 2 + 1];
                }
            }
        }
    }
}

// ===========================================================================
// Host
// ===========================================================================
extern "C" void kernel_launch(void* const* d_in, const int* in_sizes, int n_in,
                              void* d_out, int out_size) {
    (void)in_sizes; (void)n_in; (void)out_size;
    const float* x  = (const float*)d_in[0];
    const float* k0 = (const float*)d_in[1];
    const float* kh[4] = { (const float*)d_in[2], (const float*)d_in[3],
                           (const float*)d_in[4], (const float*)d_in[5] };
    const float* k5 = (const float*)d_in[6];
    const float* sl = (const float*)d_in[7];
    float* out = (float*)d_out;

    __nv_bfloat16 *aH0, *aL0, *aH1, *aL1;
    uint2* wfp;
    float* wtp;
    cudaGetSymbolAddress((void**)&aH0, g_actH0);
    cudaGetSymbolAddress((void**)&aL0, g_actL0);
    cudaGetSymbolAddress((void**)&aH1, g_actH1);
    cudaGetSymbolAddress((void**)&aL1, g_actL1);
    cudaGetSymbolAddress((void**)&wfp, g_wfrag);
    cudaGetSymbolAddress((void**)&wtp, g_wt);

    cudaFuncSetAttribute((const void*)conv4d_mma_kernel<4, false>,
                         cudaFuncAttributeMaxDynamicSharedMemorySize, HW_SMEM);
    cudaFuncSetAttribute((const void*)conv4d_mma_kernel<1, true>,
                         cudaFuncAttributeMaxDynamicSharedMemorySize, HW_SMEM);

    // ---- layer 0: direct FFMA2, split-bf16 channels-last output ----
    {
        int total = 32 * 2 * 81;
        transpose_w_kernel<<<(total + 255) / 256, 256>>>(k0, wtp, 32, 2);
        conv4d_l0_kernel<2, 2, 2, 4, 4><<<dim3(128, 8), 256>>>(x, wtp, sl + 0,
                                                               aH0, aL0);
    }

    dim3 tgrid(256, 8);
    const int PREPN = (81 * 512 + 255) / 256;

    // ---- layers 1-4: HMMA path ----
    __nv_bfloat16* inH = aH0; __nv_bfloat16* inL = aL0;
    __nv_bfloat16* otH = aH1; __nv_bfloat16* otL = aL1;
    for (int i = 0; i < 4; ++i) {
        prep_w_frag<<<PREPN, 256>>>(kh[i], 32, wfp);
        conv4d_mma_kernel<4, false><<<tgrid, 256, HW_SMEM>>>(
            inH, inL, wfp, sl + 1 + i, otH, otL, nullptr);
        __nv_bfloat16* t;
        t = inH; inH = otH; otH = t;
        t = inL; inL = otL; otL = t;
    }

    // ---- layer 5: HMMA path, only co 0..7 tile, fp32 output, no PReLU ----
    prep_w_frag<<<PREPN, 256>>>(k5, 2, wfp);
    conv4d_mma_kernel<1, true><<<tgrid, 256, HW_SMEM>>>(
        inH, inL, wfp, nullptr, nullptr, nullptr, out);
}

// round 16
// speedup vs baseline: 1.0345x; 1.0345x over previous
#include <cuda_runtime.h>
#include <cuda_bf16.h>
#include <cstdint>

// ===========================================================================
// 4D CNN (6 conv4d 3^4 SAME + 5 scalar PReLU).
// Layers 1-5: warp-level mma.sync (HMMA) implicit GEMM, per-tap K=32 GEMMs,
// fp32 accum, split-bf16 (AhBh + AhBl + AlBh). B operands from precomputed
// register-fragment tables in global. R16: keep R14's single 51.8KB buffer
// (3 CTAs/SM — load-bearing per R15 post-mortem) but stage with cp.async
// (LDGSTS): no register round-trip, no long-scoreboard chains in staging.
// Last layer computes only the n8 tile with its 2 channels.
// Layer 0 (ci=2): FFMA2 direct conv with split-output epilogue.
// ===========================================================================

static constexpr int Ld = 16;
static constexpr int SP = Ld * Ld * Ld * Ld;  // 65536

// ---- scratch (device globals: allowed) ----
__device__ __nv_bfloat16 g_actH0[8 * SP * 32];
__device__ __nv_bfloat16 g_actL0[8 * SP * 32];
__device__ __nv_bfloat16 g_actH1[8 * SP * 32];
__device__ __nv_bfloat16 g_actL1[8 * SP * 32];
__device__ uint2         g_wfrag[81 * 512];    // [tap][s][ks][nt][lane] b0,b1
__device__ float         g_wt[32 * 81 * 32];   // layer0 transposed weights

// ===========================================================================
// mma.sync / ldmatrix / cp.async helpers
// ===========================================================================
__device__ __forceinline__ uint32_t smem_to_u32(const void* p) {
    uint32_t a;
    asm("{ .reg .u64 t; cvta.to.shared.u64 t, %1; cvt.u32.u64 %0, t; }"
        : "=r"(a) : "l"(p));
    return a;
}
__device__ __forceinline__ void ldm_x4(uint32_t* r, uint32_t a) {
    asm volatile("ldmatrix.sync.aligned.m8n8.x4.shared.b16 {%0,%1,%2,%3}, [%4];"
        : "=r"(r[0]), "=r"(r[1]), "=r"(r[2]), "=r"(r[3]) : "r"(a));
}
__device__ __forceinline__ void mma_bf16(float* d, const uint32_t* a,
                                         uint32_t b0, uint32_t b1) {
    asm volatile("mma.sync.aligned.m16n8k16.row.col.f32.bf16.bf16.f32 "
        "{%0,%1,%2,%3}, {%4,%5,%6,%7}, {%8,%9}, {%0,%1,%2,%3};"
        : "+f"(d[0]), "+f"(d[1]), "+f"(d[2]), "+f"(d[3])
        : "r"(a[0]), "r"(a[1]), "r"(a[2]), "r"(a[3]), "r"(b0), "r"(b1));
}
__device__ __forceinline__ void cp16(uint32_t s, const void* g, bool ok) {
    int sz = ok ? 16 : 0;   // src_size 0 -> zero-fill 16B
    asm volatile("cp.async.cg.shared.global [%0], [%1], 16, %2;"
        :: "r"(s), "l"(g), "r"(sz));
}
#define CP_COMMIT() asm volatile("cp.async.commit_group;" ::: "memory")
#define CP_WAIT0()  asm volatile("cp.async.wait_group 0;" ::: "memory")

// ===========================================================================
// f32x2 helpers (layer 0)
// ===========================================================================
using u64 = unsigned long long;
__device__ __forceinline__ u64 dup2(float x) {
    u64 r; asm("mov.b64 %0, {%1, %1};" : "=l"(r) : "f"(x)); return r;
}
__device__ __forceinline__ u64 fma2(u64 a, u64 b, u64 c) {
    u64 d; asm("fma.rn.f32x2 %0, %1, %2, %3;" : "=l"(d) : "l"(a), "l"(b), "l"(c));
    return d;
}
__device__ __forceinline__ void unpack2(u64 v, float& lo, float& hi) {
    asm("mov.b64 {%0, %1}, %2;" : "=f"(lo), "=f"(hi) : "l"(v));
}
__device__ __forceinline__ uint32_t packbf(__nv_bfloat16 a, __nv_bfloat16 b) {
    __nv_bfloat162 t(a, b);           // a -> low 16 bits
    return *reinterpret_cast<uint32_t*>(&t);
}

// ===========================================================================
// Weight prep
// ===========================================================================
__global__ void transpose_w_kernel(const float* __restrict__ w,
                                   float* __restrict__ wt, int CO, int CI) {
    int idx = blockIdx.x * blockDim.x + threadIdx.x;
    int total = CO * CI * 81;
    if (idx >= total) return;
    int co  = idx / (CI * 81);
    int rem = idx - co * (CI * 81);
    int ci  = rem / 81;
    int tap = rem - ci * 81;
    wt[(ci * 81 + tap) * CO + co] = w[idx];
}

// W[CO][32][81] fp32 -> per-lane B fragments for mma.m16n8k16.row.col.
// [tap][split][ks][nt][lane] -> uint2; co>=CO zero-padded.
__global__ void prep_w_frag(const float* __restrict__ w, int CO,
                            uint2* __restrict__ gf) {
    int idx = blockIdx.x * blockDim.x + threadIdx.x;
    if (idx >= 81 * 512) return;
    int lane = idx & 31;
    int nt   = (idx >> 5) & 3;
    int ks   = (idx >> 7) & 1;
    int s    = (idx >> 8) & 1;
    int tap  = idx >> 9;
    int n  = nt * 8 + (lane >> 2);
    int k0 = (lane & 3) * 2 + ks * 16;
    auto valbf = [&](int ci) -> __nv_bfloat16 {
        float v = (n < CO) ? w[((size_t)n * 32 + ci) * 81 + tap] : 0.f;
        __nv_bfloat16 hi = __float2bfloat16(v);
        if (s == 0) return hi;
        return __float2bfloat16(v - __bfloat162float(hi));
    };
    uint2 r;
    r.x = packbf(valbf(k0),     valbf(k0 + 1));
    r.y = packbf(valbf(k0 + 8), valbf(k0 + 9));
    gf[idx] = r;
}

// ===========================================================================
// Layer 0: FFMA2 direct conv (ci=2), split bf16 channels-last output.
// ===========================================================================
template<int C_IN, int CI_CHUNK, int T1, int T2, int T3>
__global__ void __launch_bounds__(256)
conv4d_l0_kernel(const float* __restrict__ in,
                 const float* __restrict__ wt,
                 const float* __restrict__ slope_p,
                 __nv_bfloat16* __restrict__ outH,
                 __nv_bfloat16* __restrict__ outL)
{
    constexpr int C_OUT = 32, CO_PER = 8, CP2 = CO_PER / 2;
    constexpr int H1 = T1 + 2, H2 = T2 + 2, H3 = T3 + 2, H4 = 20;
    constexpr int VG = T1 * T2 * T3 * 2;
    constexpr int NT = VG * (C_OUT / CO_PER);
    constexpr int SMCH = H1 * H2 * H3 * H4;

    __shared__ float sx[CI_CHUNK * SMCH];

    constexpr int NB2 = 16 / T2, NB3 = 16 / T3;
    int tb = blockIdx.x;
    int b3 = tb % NB3; tb /= NB3;
    int b2 = tb % NB2; tb /= NB2;
    int b1 = tb;
    int n  = blockIdx.y;

    int tid = threadIdx.x;
    int cog = tid / VG;
    int vg  = tid - cog * VG;
    int v4h = vg & 1;
    int t   = vg >> 1;
    int v3  = t % T3; t /= T3;
    int v2  = t % T2; t /= T2;
    int v1  = t;
    int co0 = cog * CO_PER;

    u64 accP[CP2][8];
#pragma unroll
    for (int c2 = 0; c2 < CP2; ++c2)
#pragma unroll
        for (int j = 0; j < 8; ++j) accP[c2][j] = 0ull;

    const float* inb = in + (size_t)n * C_IN * SP;

    for (int cc = 0; cc < C_IN; cc += CI_CHUNK) {
        __syncthreads();
        constexpr int LOADN = CI_CHUNK * H1 * H2 * H3 * 18;
        for (int idx = tid; idx < LOADN; idx += NT) {
            int i4 = idx % 18; int r = idx / 18;
            int i3 = r % H3; r /= H3;
            int i2 = r % H2; r /= H2;
            int i1 = r % H1; r /= H1;
            int g1 = b1 * T1 - 1 + i1, g2 = b2 * T2 - 1 + i2;
            int g3 = b3 * T3 - 1 + i3, g4 = i4 - 1;
            float v = 0.f;
            if ((unsigned)g1 < 16u && (unsigned)g2 < 16u &&
                (unsigned)g3 < 16u && (unsigned)g4 < 16u)
                v = inb[(size_t)(cc + r) * SP +
                        (((g1 * 16 + g2) * 16 + g3) * 16 + g4)];
            sx[r * SMCH + ((i1 * H2 + i2) * H3 + i3) * H4 + i4] = v;
        }
        __syncthreads();

#pragma unroll 1
        for (int ci = 0; ci < CI_CHUNK; ++ci) {
            const float* wp = wt + ((size_t)(cc + ci) * 81) * C_OUT + co0;
            const float* sc = sx + ci * SMCH;
#pragma unroll 1
            for (int o1 = 0; o1 < 3; ++o1)
#pragma unroll 1
            for (int o2 = 0; o2 < 3; ++o2)
#pragma unroll 1
            for (int o3 = 0; o3 < 3; ++o3) {
                const float* srow =
                    sc + (((v1 + o1) * H2 + (v2 + o2)) * H3 + (v3 + o3)) * H4
                       + v4h * 8;
                u64 rxd[10];
#pragma unroll
                for (int j = 0; j < 10; ++j) rxd[j] = dup2(srow[j]);
                const float* wo = wp + (((o1 * 3 + o2) * 3 + o3) * 3) * C_OUT;
#pragma unroll
                for (int o4 = 0; o4 < 3; ++o4) {
                    const u64* wp64 = reinterpret_cast<const u64*>(wo + o4 * C_OUT);
                    u64 w2[CP2];
#pragma unroll
                    for (int c2 = 0; c2 < CP2; ++c2) w2[c2] = wp64[c2];
#pragma unroll
                    for (int j = 0; j < 8; ++j)
#pragma unroll
                        for (int c2 = 0; c2 < CP2; ++c2)
                            accP[c2][j] = fma2(w2[c2], rxd[j + o4], accP[c2][j]);
                }
            }
        }
    }

    float acc[CO_PER][8];
#pragma unroll
    for (int c2 = 0; c2 < CP2; ++c2)
#pragma unroll
        for (int j = 0; j < 8; ++j)
            unpack2(accP[c2][j], acc[2 * c2][j], acc[2 * c2 + 1][j]);

    float slope = *slope_p;
    int d1 = b1 * T1 + v1, d2 = b2 * T2 + v2, d3 = b3 * T3 + v3;
    size_t sidx = (((size_t)d1 * 16 + d2) * 16 + d3) * 16 + v4h * 8;

#pragma unroll
    for (int j = 0; j < 8; ++j) {
        uint32_t HW[4], LW[4];
#pragma unroll
        for (int w = 0; w < 4; ++w) {
            float v0 = acc[2 * w][j], v1 = acc[2 * w + 1][j];
            v0 = (v0 < 0.f) ? slope * v0 : v0;
            v1 = (v1 < 0.f) ? slope * v1 : v1;
            __nv_bfloat16 h0 = __float2bfloat16(v0);
            __nv_bfloat16 h1 = __float2bfloat16(v1);
            float l0 = v0 - __bfloat162float(h0);
            float l1 = v1 - __bfloat162float(h1);
            HW[w] = packbf(h0, h1);
            LW[w] = packbf(__float2bfloat16(l0), __float2bfloat16(l1));
        }
        size_t e = ((size_t)n * SP + sidx + j) * 32 + co0;
        *reinterpret_cast<uint4*>(outH + e) = *reinterpret_cast<uint4*>(HW);
        *reinterpret_cast<uint4*>(outL + e) = *reinterpret_cast<uint4*>(LW);
    }
}

// ===========================================================================
// HMMA conv layer (ci=32): per-tap m16n8k16 MMAs, fp32 register accum.
// CTA = one (n, d1, d2) plane -> 256 positions. Warp w owns d3 rows
// {2w, 2w+1}. B fragments from global frag table (uniform LDG broadcast).
// Staging via cp.async into a SINGLE 51840B buffer (3 CTAs/SM preserved):
// sync -> LDGSTS issue -> wait -> sync -> compute. No LDG register
// round-trips or long-scoreboard chains in the staging path.
// ===========================================================================
static constexpr int HW_LO   = 25920;
static constexpr int HW_SMEM = 51840;

template<int NTT, bool LAST>
__global__ void __launch_bounds__(256, 3)
conv4d_mma_kernel(const __nv_bfloat16* __restrict__ aH,
                  const __nv_bfloat16* __restrict__ aL,
                  const uint2* __restrict__ wf,
                  const float* __restrict__ slope_p,
                  __nv_bfloat16* __restrict__ oH,
                  __nv_bfloat16* __restrict__ oL,
                  float* __restrict__ oF)
{
    extern __shared__ char sm[];
    const uint32_t sb = smem_to_u32(sm);

    int tid  = threadIdx.x;
    int wid  = tid >> 5;
    int lane = tid & 31;
    int lrow = lane & 15;
    uint32_t laneA = (uint32_t)lrow * 80 + ((lane >> 4) & 1) * 16;

    int n  = blockIdx.y;
    int d1 = blockIdx.x >> 4, d2 = blockIdx.x & 15;
    const size_t nbase = (size_t)n * SP;

    float d[2][NTT][4];
#pragma unroll
    for (int m = 0; m < 2; ++m)
#pragma unroll
        for (int nt = 0; nt < NTT; ++nt)
#pragma unroll
            for (int r = 0; r < 4; ++r) d[m][nt][r] = 0.f;

#pragma unroll 1
    for (int o12 = 0; o12 < 9; ++o12) {
        int o1 = o12 / 3, o2 = o12 - (o12 / 3) * 3;
        __syncthreads();                 // previous phase's MMAs done with smem
        // ---- stage slice [18 d3][18 d4][32 ci] hi & lo via cp.async ----
        {
            int g1 = d1 + o1 - 1, g2 = d2 + o2 - 1;
            bool rowok = ((unsigned)g1 < 16u) && ((unsigned)g2 < 16u);
            for (int i = tid; i < 1296; i += 256) {   // 324 pts x 4 16B-chunks
                int pt = i >> 2, ch = i & 3;
                int s3 = pt / 18, s4 = pt - s3 * 18;
                int g3 = s3 - 1, g4 = s4 - 1;
                bool ok = rowok && (unsigned)g3 < 16u && (unsigned)g4 < 16u;
                size_t p = 0;
                if (ok) p = nbase + (size_t)(((g1 * 16 + g2) * 16 + g3) * 16 + g4);
                uint32_t so = sb + (uint32_t)(pt * 80 + ch * 16);
                cp16(so,         (const char*)(aH + p * 32) + ch * 16, ok);
                cp16(so + HW_LO, (const char*)(aL + p * 32) + ch * 16, ok);
            }
            CP_COMMIT();
            CP_WAIT0();
        }
        __syncthreads();                 // slice visible to all warps

#pragma unroll 1
        for (int o3 = 0; o3 < 3; ++o3)
#pragma unroll 1
        for (int o4 = 0; o4 < 3; ++o4) {
            int tap = o12 * 9 + o3 * 3 + o4;
            const uint2* wfH = wf + (size_t)tap * 512 + lane;
            const uint2* wfL = wfH + 256;
            int pr0 = ((wid * 2 + 0 + o3) * 18 + o4) * 80;
            uint32_t aH0 = sb + pr0 + laneA;
            uint32_t aH1 = aH0 + 1440;               // +1 d3 row (18*80)
            uint32_t aL0 = aH0 + HW_LO;
            uint32_t aL1 = aL0 + 1440;

#pragma unroll
            for (int ks = 0; ks < 2; ++ks) {
                uint2 BH[NTT], BL[NTT];
#pragma unroll
                for (int nt = 0; nt < NTT; ++nt) {
                    BH[nt] = wfH[ks * 128 + nt * 32];
                    BL[nt] = wfL[ks * 128 + nt * 32];
                }
                uint32_t ah[2][4], al[2][4];
                ldm_x4(ah[0], aH0 + ks * 32);
                ldm_x4(ah[1], aH1 + ks * 32);
                ldm_x4(al[0], aL0 + ks * 32);
                ldm_x4(al[1], aL1 + ks * 32);
#pragma unroll
                for (int m = 0; m < 2; ++m)
#pragma unroll
                    for (int nt = 0; nt < NTT; ++nt) {
                        mma_bf16(d[m][nt], ah[m], BH[nt].x, BH[nt].y);
                        mma_bf16(d[m][nt], ah[m], BL[nt].x, BL[nt].y);
                        mma_bf16(d[m][nt], al[m], BH[nt].x, BH[nt].y);
                    }
            }
        }
    }

    // ---- epilogue ----
    int gID = lane >> 2, tig = lane & 3;
    if (!LAST) {
        float slope = *slope_p;
#pragma unroll
        for (int m = 0; m < 2; ++m) {
            int p3 = wid * 2 + m;
#pragma unroll
            for (int nt = 0; nt < NTT; ++nt) {
                int co = nt * 8 + tig * 2;
#pragma unroll
                for (int rr = 0; rr < 2; ++rr) {
                    int p4 = gID + rr * 8;
                    float v0 = d[m][nt][rr * 2 + 0];
                    float v1 = d[m][nt][rr * 2 + 1];
                    v0 = (v0 < 0.f) ? slope * v0 : v0;
                    v1 = (v1 < 0.f) ? slope * v1 : v1;
                    __nv_bfloat16 h0 = __float2bfloat16(v0);
                    __nv_bfloat16 h1 = __float2bfloat16(v1);
                    float l0 = v0 - __bfloat162float(h0);
                    float l1 = v1 - __bfloat162float(h1);
                    size_t pg = (size_t)(((d1 * 16 + d2) * 16 + p3) * 16 + p4);
                    size_t e = (nbase + pg) * 32 + co;
                    *reinterpret_cast<uint32_t*>(oH + e) = packbf(h0, h1);
                    *reinterpret_cast<uint32_t*>(oL + e) =
                        packbf(__float2bfloat16(l0), __float2bfloat16(l1));
                }
            }
        }
    } else {
        if (tig == 0) {
#pragma unroll
            for (int m = 0; m < 2; ++m) {
                int p3 = wid * 2 + m;
#pragma unroll
                for (int rr = 0; rr < 2; ++rr) {
                    int p4 = gID + rr * 8;
                    size_t pg = (size_t)(((d1 * 16 + d2) * 16 + p3) * 16 + p4);
                    oF[(size_t)n * 2 * SP + pg]      = d[m][0][rr * 2 + 0];
                    oF[(size_t)n * 2 * SP + SP + pg] = d[m][0][rr * 2 + 1];
                }
            }
        }
    }
}

// ===========================================================================
// Host
// ===========================================================================
extern "C" void kernel_launch(void* const* d_in, const int* in_sizes, int n_in,
                              void* d_out, int out_size) {
    (void)in_sizes; (void)n_in; (void)out_size;
    const float* x  = (const float*)d_in[0];
    const float* k0 = (const float*)d_in[1];
    const float* kh[4] = { (const float*)d_in[2], (const float*)d_in[3],
                           (const float*)d_in[4], (const float*)d_in[5] };
    const float* k5 = (const float*)d_in[6];
    const float* sl = (const float*)d_in[7];
    float* out = (float*)d_out;

    __nv_bfloat16 *aH0, *aL0, *aH1, *aL1;
    uint2* wfp;
    float* wtp;
    cudaGetSymbolAddress((void**)&aH0, g_actH0);
    cudaGetSymbolAddress((void**)&aL0, g_actL0);
    cudaGetSymbolAddress((void**)&aH1, g_actH1);
    cudaGetSymbolAddress((void**)&aL1, g_actL1);
    cudaGetSymbolAddress((void**)&wfp, g_wfrag);
    cudaGetSymbolAddress((void**)&wtp, g_wt);

    cudaFuncSetAttribute((const void*)conv4d_mma_kernel<4, false>,
                         cudaFuncAttributeMaxDynamicSharedMemorySize, HW_SMEM);
    cudaFuncSetAttribute((const void*)conv4d_mma_kernel<1, true>,
                         cudaFuncAttributeMaxDynamicSharedMemorySize, HW_SMEM);

    // ---- layer 0: direct FFMA2, split-bf16 channels-last output ----
    {
        int total = 32 * 2 * 81;
        transpose_w_kernel<<<(total + 255) / 256, 256>>>(k0, wtp, 32, 2);
        conv4d_l0_kernel<2, 2, 2, 4, 4><<<dim3(128, 8), 256>>>(x, wtp, sl + 0,
                                                               aH0, aL0);
    }

    dim3 tgrid(256, 8);
    const int PREPN = (81 * 512 + 255) / 256;

    // ---- layers 1-4: HMMA path ----
    __nv_bfloat16* inH = aH0; __nv_bfloat16* inL = aL0;
    __nv_bfloat16* otH = aH1; __nv_bfloat16* otL = aL1;
    for (int i = 0; i < 4; ++i) {
        prep_w_frag<<<PREPN, 256>>>(kh[i], 32, wfp);
        conv4d_mma_kernel<4, false><<<tgrid, 256, HW_SMEM>>>(
            inH, inL, wfp, sl + 1 + i, otH, otL, nullptr);
        __nv_bfloat16* t;
        t = inH; inH = otH; otH = t;
        t = inL; inL = otL; otL = t;
    }

    // ---- layer 5: HMMA path, only co 0..7 tile, fp32 output, no PReLU ----
    prep_w_frag<<<PREPN, 256>>>(k5, 2, wfp);
    conv4d_mma_kernel<1, true><<<tgrid, 256, HW_SMEM>>>(
        inH, inL, wfp, nullptr, nullptr, nullptr, out);
}